// round 9
// baseline (speedup 1.0000x reference)
#include <cuda_runtime.h>
#include <cuda_bf16.h>

#define NUM_BINS 32
#define NBINS2   (NUM_BINS * NUM_BINS)
#define NTHREADS 1024
#define SMEM_BYTES (NBINS2 * 32 * 4)   // 128 KB: 32 lane-replicas per bin
#define EPS 1e-5f

// Zero-initialized device globals. Invariant: g_hist == 0 and g_done == 0 at
// kernel entry; the last CTA restores this before exit (deterministic replays).
__device__ unsigned int g_hist[NBINS2];
__device__ unsigned int g_done;

// Inputs are exact integers 0..255 stored as fp32. bin = rint(v/255*31).
// v*31/255 is never exactly k+0.5, and the nearest tie distance (1/510) far
// exceeds the fp32 error of v*fl(31/255) (~7e-6), so floor(v*c + 0.5) is
// bit-identical to the reference binning (verified rel_err == 0.0).
__device__ __forceinline__ int bin_of(float v) {
    const float c = 31.0f / 255.0f;
    return (int)__fmaf_rn(v, c, 0.5f);   // FFMA + F2I; truncation == floor (v>=0)
}

// Per-lane replica: counter for bin b, lane l lives at sh[b*32 + l].
// bank = (b*32 + l) % 32 = l  ->  every warp atomic is conflict-free (1 phase).
__device__ __forceinline__ void accum4(unsigned int* __restrict__ shl,
                                       float4 a, float4 b) {
    atomicAdd(&shl[(bin_of(a.x) * NUM_BINS + bin_of(b.x)) << 5], 1u);
    atomicAdd(&shl[(bin_of(a.y) * NUM_BINS + bin_of(b.y)) << 5], 1u);
    atomicAdd(&shl[(bin_of(a.z) * NUM_BINS + bin_of(b.z)) << 5], 1u);
    atomicAdd(&shl[(bin_of(a.w) * NUM_BINS + bin_of(b.w)) << 5], 1u);
}

__global__ void __launch_bounds__(NTHREADS, 1) lmi_fused_kernel(
    const float4* __restrict__ I4,
    const float4* __restrict__ J4,
    int n4,
    float inv_total,
    float* __restrict__ out)
{
    extern __shared__ unsigned int sh[];   // [NBINS2 * 32]
    const int t    = threadIdx.x;
    const int lane = t & 31;
    const int warp = t >> 5;
    unsigned int* shl = &sh[lane];         // this lane's replica column

    // ---- zero 128 KB of smem (8 x uint4 per thread) ----
    uint4* sh4 = (uint4*)sh;
    #pragma unroll
    for (int k = 0; k < 8; k++)
        sh4[t + k * NTHREADS] = make_uint4(0u, 0u, 0u, 0u);
    __syncthreads();

    // ---- Phase 1: histogram (2x unrolled grid-stride, 4 LDG.128 in flight) ----
    const int stride = gridDim.x * blockDim.x;
    int i = blockIdx.x * blockDim.x + t;
    for (; i + stride < n4; i += 2 * stride) {
        float4 a0 = __ldcs(&I4[i]);
        float4 b0 = __ldcs(&J4[i]);
        float4 a1 = __ldcs(&I4[i + stride]);
        float4 b1 = __ldcs(&J4[i + stride]);
        accum4(shl, a0, b0);
        accum4(shl, a1, b1);
    }
    if (i < n4) {
        float4 a0 = __ldcs(&I4[i]);
        float4 b0 = __ldcs(&J4[i]);
        accum4(shl, a0, b0);
    }
    __syncthreads();

    // ---- Phase 2: flush. Warp w reduces bins [w*32, w*32+32). For each bin,
    // the warp reads its 32 lane-replicas (conflict-free: bank==lane), sums
    // with REDUX, lane 0 does one global atomic. ----
    #pragma unroll 4
    for (int k = 0; k < 32; k++) {
        int b = (warp << 5) + k;
        unsigned int v = sh[(b << 5) + lane];
        unsigned int s = __reduce_add_sync(0xFFFFFFFFu, v);
        if (lane == 0 && s) atomicAdd(&g_hist[b], s);
    }

    // ---- Phase 3: last CTA computes MI, writes out, resets state ----
    __shared__ bool is_last;
    __threadfence();   // order flush atomics before the counter
    if (t == 0) {
        unsigned int done = atomicAdd(&g_done, 1u);
        is_last = (done == gridDim.x - 1);
    }
    __syncthreads();
    if (!is_last) return;

    float* jp   = (float*)sh;            // [NBINS2]
    float* rowp = jp + NBINS2;           // [32]
    float* colp = rowp + NUM_BINS;       // [32]
    float* wsum = colp + NUM_BINS;       // [32]

    {
        unsigned int v = __ldcg(&g_hist[t]);   // bypass L1: atomics are in L2
        jp[t] = (float)v * inv_total;
        g_hist[t] = 0u;                        // restore invariant for next replay
        if (t == 0) g_done = 0u;
    }
    __syncthreads();

    if (t < NUM_BINS) {
        float s = 0.0f;
        #pragma unroll
        for (int c = 0; c < NUM_BINS; c++) s += jp[t * NUM_BINS + c];
        rowp[t] = s;
    } else if (t < 2 * NUM_BINS) {
        int c = t - NUM_BINS;
        float s = 0.0f;
        #pragma unroll
        for (int r = 0; r < NUM_BINS; r++) s += jp[r * NUM_BINS + c];
        colp[c] = s;
    }
    __syncthreads();

    float p  = jp[t];
    float pi = rowp[t >> 5];
    float pj = colp[t & 31];
    float term = p * (logf(p + EPS) - logf(pi + EPS) - logf(pj + EPS));

    #pragma unroll
    for (int off = 16; off > 0; off >>= 1)
        term += __shfl_xor_sync(0xFFFFFFFFu, term, off);
    if (lane == 0) wsum[warp] = term;
    __syncthreads();
    if (t < 32) {
        float s = wsum[t];
        #pragma unroll
        for (int off = 16; off > 0; off >>= 1)
            s += __shfl_xor_sync(0xFFFFFFFFu, s, off);
        if (t == 0) {
            out[0] = 1.0f / (1.0f + expf(s));   // sigmoid(-mi)
        }
    }
}

extern "C" void kernel_launch(void* const* d_in, const int* in_sizes, int n_in,
                              void* d_out, int out_size)
{
    const float* I = (const float*)d_in[0];
    const float* J = (const float*)d_in[1];
    float* out = (float*)d_out;
    const int n  = in_sizes[0];   // 33,554,432
    const int n4 = n / 4;

    cudaFuncSetAttribute(lmi_fused_kernel,
                         cudaFuncAttributeMaxDynamicSharedMemorySize, SMEM_BYTES);

    int nsm = 148;
    cudaDeviceGetAttribute(&nsm, cudaDevAttrMultiProcessorCount, 0);

    // one 1024-thread CTA per SM (128 KB smem each), grid-stride over data
    lmi_fused_kernel<<<nsm, NTHREADS, SMEM_BYTES>>>(
        (const float4*)I, (const float4*)J, n4, 1.0f / (float)n, out);
}